// round 13
// baseline (speedup 1.0000x reference)
#include <cuda_runtime.h>
#include <cuda_bf16.h>
#include <cuda_fp16.h>
#include <math.h>
#include <stdint.h>

// ---------------------------------------------------------------------------
// Problem constants
// ---------------------------------------------------------------------------
#define BATCH   8
#define HH      112
#define CC      192
#define WS      7
#define SHIFT   3
#define NHD     6
#define HDIM    32
#define NTK     49
#define NWIN    2048
#define MROWS   100352
#define LTOK    12544
#define HID     768
#define TOKF    19267584ull        // MROWS*CC floats
#define LOG100F 4.6051701859880914f

// ---------------------------------------------------------------------------
// Scratch: ONE static device slab.
//  [0,T)   hwin (alias attno)   [T,4T) qkv q|k|v (q aliased by proj)
//  [4T,5T) h1   [5T,9T) mlp1    [9T,10T) mlp2
// ---------------------------------------------------------------------------
__device__ float g_scratch[10ull * TOKF];
__device__ float g_cpb[169 * NHD];
__device__ float g_rpb[NHD * NTK * NTK];
__device__ float g_wqkv[CC * 3 * CC];     // packed [k][n], n: q|k|v (192x576)
__device__ float g_bqkv[3 * CC];

#define OFF_HWIN  (0ull * TOKF)
#define OFF_QKV   (1ull * TOKF)
#define OFF_ATTNO (0ull * TOKF)
#define OFF_PROJ  (1ull * TOKF)
#define OFF_H1    (4ull * TOKF)
#define OFF_MLP1  (5ull * TOKF)
#define OFF_MLP2  (9ull * TOKF)

// ---------------------------------------------------------------------------
// CPB MLP + rpb expansion
// ---------------------------------------------------------------------------
__device__ __forceinline__ float rel_coord(int a) {
    float ch = (float)(a - (WS - 1));
    float t  = ch / (float)(WS - 1) * 8.0f;
    float v  = log2f(fabsf(t) + 1.0f) / log2f(8.0f);
    return (t > 0.f) ? v : ((t < 0.f) ? -v : 0.f);
}
__global__ void cpb_kernel(const float* __restrict__ w0, const float* __restrict__ b0,
                           const float* __restrict__ w1) {
    int idx = blockIdx.x * blockDim.x + threadIdx.x;
    if (idx >= 169 * NHD) return;
    int t = idx / NHD, h = idx % NHD;
    float c0 = rel_coord(t / 13);
    float c1 = rel_coord(t % 13);
    float s = 0.f;
    for (int j = 0; j < 512; ++j) {
        float hid = fmaf(c0, w0[j], fmaf(c1, w0[512 + j], b0[j]));
        hid = fmaxf(hid, 0.f);
        s = fmaf(hid, w1[j * NHD + h], s);
    }
    g_cpb[idx] = 16.0f / (1.0f + expf(-s));
}
__global__ void rpb_kernel() {
    int idx = blockIdx.x * blockDim.x + threadIdx.x;
    if (idx >= NHD * NTK * NTK) return;
    int h = idx / (NTK * NTK), e = idx % (NTK * NTK);
    int i = e / NTK, j = e % NTK;
    int r0 = i / WS - j / WS + (WS - 1);
    int r1 = i % WS - j % WS + (WS - 1);
    g_rpb[idx] = g_cpb[(r0 * 13 + r1) * NHD + h];
}

// ---------------------------------------------------------------------------
// Pack q|k|v weights into one [192][576] matrix + fused bias (k bias = 0)
// ---------------------------------------------------------------------------
__global__ void packw_kernel(const float* __restrict__ q_w, const float* __restrict__ q_b,
                             const float* __restrict__ k_w, const float* __restrict__ v_w,
                             const float* __restrict__ v_b) {
    int idx = blockIdx.x * 256 + threadIdx.x;
    if (idx < CC * 3 * CC) {
        int k = idx / (3 * CC), n = idx % (3 * CC);
        float v = (n < CC) ? q_w[k * CC + n]
                : (n < 2 * CC) ? k_w[k * CC + n - CC]
                : v_w[k * CC + n - 2 * CC];
        g_wqkv[idx] = v;
    }
    if (idx < 3 * CC) {
        g_bqkv[idx] = (idx < CC) ? q_b[idx] : (idx < 2 * CC) ? 0.f : v_b[idx - 2 * CC];
    }
}

// ---------------------------------------------------------------------------
// Shift + window partition gather (float4 wide)
// ---------------------------------------------------------------------------
__global__ void gather_kernel(const float4* __restrict__ x, float4* __restrict__ hwin) {
    int idx = blockIdx.x * 256 + threadIdx.x;                 // over MROWS*48
    if (idx >= MROWS * 48) return;
    int m = idx / 48, c4 = idx % 48;
    int w = m / NTK, n = m % NTK;
    int b = w >> 8, widx = w & 255;
    int wh = widx >> 4, ww = widx & 15;
    int gh = wh * WS + n / WS + SHIFT; if (gh >= HH) gh -= HH;
    int gw = ww * WS + n % WS + SHIFT; if (gw >= HH) gw -= HH;
    hwin[idx] = x[((size_t)(b * LTOK + gh * HH + gw)) * 48 + c4];
}

// ---------------------------------------------------------------------------
// Tensor-core GEMM, fp32 in/out. 128x64 CTA tile, 4 warps, warp tile 64x32.
// MODE 0: bf16 3-term split (C = AH*BL + AL*BH + AH*BH), ~16 mantissa bits.
// MODE 1: fp16 1-term (~11 bits) — MLP only.
// BK=16, m16n8k16 fp32-accum, double-buffered smem, 1 sync per k-tile.
// Per warp per k-tile: MODE0 48 LDS / 48 MMA; MODE1 24 LDS / 16 MMA.
// ---------------------------------------------------------------------------
#define TBM 128
#define TBN 64
#define GBK 16
#define ASTR 136
#define BSTR 72

enum { EPI_PLAIN = 0, EPI_GELU = 1, EPI_PROJ = 2, EPI_QKV = 3 };

__device__ __forceinline__ float gelu_tanh(float x) {
    float x3 = x * x * x;
    return 0.5f * x * (1.0f + tanhf(0.7978845608028654f * (x + 0.044715f * x3)));
}
__device__ __forceinline__ void splitpair(float v0, float v1, uint32_t& hi, uint32_t& lo) {
    __nv_bfloat16 h0 = __float2bfloat16_rn(v0);
    __nv_bfloat16 h1 = __float2bfloat16_rn(v1);
    __nv_bfloat16 l0 = __float2bfloat16_rn(v0 - __bfloat162float(h0));
    __nv_bfloat16 l1 = __float2bfloat16_rn(v1 - __bfloat162float(h1));
    hi = (uint32_t)__bfloat16_as_ushort(h0) | ((uint32_t)__bfloat16_as_ushort(h1) << 16);
    lo = (uint32_t)__bfloat16_as_ushort(l0) | ((uint32_t)__bfloat16_as_ushort(l1) << 16);
}
__device__ __forceinline__ uint32_t h2pack(float v0, float v1) {
    __half2 h = __floats2half2_rn(v0, v1);
    return *(uint32_t*)&h;
}
__device__ __forceinline__ void mma_bf16(float c[4], const uint32_t a[4], const uint32_t b[2]) {
    asm volatile(
        "mma.sync.aligned.m16n8k16.row.col.f32.bf16.bf16.f32 "
        "{%0,%1,%2,%3}, {%4,%5,%6,%7}, {%8,%9}, {%0,%1,%2,%3};\n"
        : "+f"(c[0]), "+f"(c[1]), "+f"(c[2]), "+f"(c[3])
        : "r"(a[0]), "r"(a[1]), "r"(a[2]), "r"(a[3]), "r"(b[0]), "r"(b[1]));
}
__device__ __forceinline__ void mma_fp16(float c[4], const uint32_t a[4], const uint32_t b[2]) {
    asm volatile(
        "mma.sync.aligned.m16n8k16.row.col.f32.f16.f16.f32 "
        "{%0,%1,%2,%3}, {%4,%5,%6,%7}, {%8,%9}, {%0,%1,%2,%3};\n"
        : "+f"(c[0]), "+f"(c[1]), "+f"(c[2]), "+f"(c[3])
        : "r"(a[0]), "r"(a[1]), "r"(a[2]), "r"(a[3]), "r"(b[0]), "r"(b[1]));
}

template <int EPI, int MODE>
__global__ __launch_bounds__(128) void gemm_tc(
    const float* __restrict__ A, const float* __restrict__ Bm,
    const float* __restrict__ bias, float* __restrict__ Cout,
    int Nn, int K)
{
    __shared__ uint32_t AsH[2][8][ASTR];
    __shared__ uint32_t BsH[2][8][BSTR];
    __shared__ uint32_t AsL[MODE == 0 ? 2 : 1][MODE == 0 ? 8 : 1][MODE == 0 ? ASTR : 1];
    __shared__ uint32_t BsL[MODE == 0 ? 2 : 1][MODE == 0 ? 8 : 1][MODE == 0 ? BSTR : 1];

    int tid  = threadIdx.x;
    int lane = tid & 31;
    int wrp  = tid >> 5;              // 0..3
    int warpM = wrp >> 1;             // 0..1 (64-row slabs)
    int warpN = wrp & 1;              // 0..1 (32-col slabs)
    int gr = lane >> 2, tc = lane & 3;
    int bm = blockIdx.y, bn = blockIdx.x;

    // A loader: one row per thread, full 16-wide k-tile (4 x float4)
    const float* Ap = A + ((size_t)bm * TBM + tid) * K;
    // B loader: col = tid&63, k-half = tid>>6 (4 k-pairs each, 8 scalars)
    int bcol = tid & 63, ksel = tid >> 6;
    const float* Bp = Bm + (size_t)bn * TBN + bcol;

    float acc[4][4][4];
#pragma unroll
    for (int mi = 0; mi < 4; ++mi)
#pragma unroll
        for (int ni = 0; ni < 4; ++ni)
#pragma unroll
            for (int e = 0; e < 4; ++e) acc[mi][ni][e] = 0.f;

    float raf[16];
    float rb[8];

    auto LOAD = [&](int k0) {
        *(float4*)(raf)      = *(const float4*)(Ap + k0);
        *(float4*)(raf + 4)  = *(const float4*)(Ap + k0 + 4);
        *(float4*)(raf + 8)  = *(const float4*)(Ap + k0 + 8);
        *(float4*)(raf + 12) = *(const float4*)(Ap + k0 + 12);
#pragma unroll
        for (int j = 0; j < 4; ++j) {
            int kp = ksel * 4 + j;
            rb[2 * j]     = Bp[(size_t)(k0 + 2 * kp)     * Nn];
            rb[2 * j + 1] = Bp[(size_t)(k0 + 2 * kp + 1) * Nn];
        }
    };
    auto STORE = [&](int s) {
        if constexpr (MODE == 0) {
            uint32_t h, l;
#pragma unroll
            for (int i = 0; i < 8; ++i) {
                splitpair(raf[2 * i], raf[2 * i + 1], h, l);
                AsH[s][i][tid] = h; AsL[s][i][tid] = l;
            }
#pragma unroll
            for (int j = 0; j < 4; ++j) {
                int kp = ksel * 4 + j;
                splitpair(rb[2 * j], rb[2 * j + 1], h, l);
                BsH[s][kp][bcol] = h; BsL[s][kp][bcol] = l;
            }
        } else {
#pragma unroll
            for (int i = 0; i < 8; ++i)
                AsH[s][i][tid] = h2pack(raf[2 * i], raf[2 * i + 1]);
#pragma unroll
            for (int j = 0; j < 4; ++j) {
                int kp = ksel * 4 + j;
                BsH[s][kp][bcol] = h2pack(rb[2 * j], rb[2 * j + 1]);
            }
        }
    };
    auto COMP = [&](int s) {
        uint32_t aH[4][4], bH[4][2];
#pragma unroll
        for (int mi = 0; mi < 4; ++mi) {
            int r0 = warpM * 64 + mi * 16 + gr;
            aH[mi][0] = AsH[s][tc][r0];     aH[mi][1] = AsH[s][tc][r0 + 8];
            aH[mi][2] = AsH[s][tc + 4][r0]; aH[mi][3] = AsH[s][tc + 4][r0 + 8];
        }
#pragma unroll
        for (int ni = 0; ni < 4; ++ni) {
            int c0 = warpN * 32 + ni * 8 + gr;
            bH[ni][0] = BsH[s][tc][c0]; bH[ni][1] = BsH[s][tc + 4][c0];
        }
        if constexpr (MODE == 0) {
            uint32_t aL[4][4], bL[4][2];
#pragma unroll
            for (int mi = 0; mi < 4; ++mi) {
                int r0 = warpM * 64 + mi * 16 + gr;
                aL[mi][0] = AsL[s][tc][r0];     aL[mi][1] = AsL[s][tc][r0 + 8];
                aL[mi][2] = AsL[s][tc + 4][r0]; aL[mi][3] = AsL[s][tc + 4][r0 + 8];
            }
#pragma unroll
            for (int ni = 0; ni < 4; ++ni) {
                int c0 = warpN * 32 + ni * 8 + gr;
                bL[ni][0] = BsL[s][tc][c0]; bL[ni][1] = BsL[s][tc + 4][c0];
            }
#pragma unroll
            for (int mi = 0; mi < 4; ++mi)
#pragma unroll
                for (int ni = 0; ni < 4; ++ni) {
                    mma_bf16(acc[mi][ni], aH[mi], bL[ni]);
                    mma_bf16(acc[mi][ni], aL[mi], bH[ni]);
                    mma_bf16(acc[mi][ni], aH[mi], bH[ni]);
                }
        } else {
#pragma unroll
            for (int mi = 0; mi < 4; ++mi)
#pragma unroll
                for (int ni = 0; ni < 4; ++ni)
                    mma_fp16(acc[mi][ni], aH[mi], bH[ni]);
        }
    };

    int iters = K / GBK;
    LOAD(0);
    STORE(0);
    __syncthreads();
    for (int it = 0; it < iters; ++it) {
        int cur = it & 1;
        if (it + 1 < iters) LOAD((it + 1) * GBK);
        COMP(cur);
        if (it + 1 < iters) STORE(cur ^ 1);
        __syncthreads();
    }

    // epilogue
#pragma unroll
    for (int mi = 0; mi < 4; ++mi) {
        int rbase = bm * TBM + warpM * 64 + mi * 16 + gr;
#pragma unroll
        for (int ni = 0; ni < 4; ++ni) {
            int cbase = bn * TBN + warpN * 32 + ni * 8 + 2 * tc;
#pragma unroll
            for (int e = 0; e < 4; ++e) {
                int row = rbase + (e >> 1) * 8;
                int col = cbase + (e & 1);
                float v = acc[mi][ni][e] + bias[col];
                if constexpr (EPI == EPI_PLAIN) {
                    Cout[(size_t)row * Nn + col] = v;
                } else if constexpr (EPI == EPI_GELU) {
                    Cout[(size_t)row * Nn + col] = gelu_tanh(v);
                } else if constexpr (EPI == EPI_PROJ) {
                    int w = row / NTK, n = row % NTK;
                    int b = w >> 8, widx = w & 255;
                    int wh = widx >> 4, ww = widx & 15;
                    int gh = wh * WS + n / WS + SHIFT; if (gh >= HH) gh -= HH;
                    int gw = ww * WS + n % WS + SHIFT; if (gw >= HH) gw -= HH;
                    Cout[((size_t)(b * LTOK + gh * HH + gw)) * CC + col] = v;
                } else {  // EPI_QKV: col in [0,576); mat = col/192
                    int mat = col / CC, c = col - mat * CC;
                    int head = c >> 5, d = c & 31;
                    int w = row / NTK, n = row % NTK;
                    size_t off = (size_t)mat * TOKF +
                                 (((size_t)w * NHD + head) * NTK + n) * HDIM + d;
                    Cout[off] = v;
                }
            }
        }
    }
}

// ---------------------------------------------------------------------------
// Attention: fused q/k cosine-normalize + scores + softmax + PV (all fp32).
// ---------------------------------------------------------------------------
__global__ __launch_bounds__(256) void attn_kernel(
    const float* __restrict__ qkv, const float* __restrict__ logit_scale,
    float* __restrict__ out)
{
    __shared__ float sq[NTK * HDIM];
    __shared__ float skT[HDIM * 50];
    __shared__ float sv[NTK * HDIM];
    __shared__ float sS[NTK * 50];

    int bid = blockIdx.x;
    int w = bid / NHD, hd = bid % NHD;
    size_t base = ((size_t)w * NHD + hd) * (NTK * HDIM);
    const float* qp = qkv + base;
    const float* kp = qkv + TOKF + base;
    const float* vp = qkv + 2ull * TOKF + base;

    int tid = threadIdx.x;
    for (int i = tid; i < NTK * HDIM; i += 256) {
        sq[i] = qp[i];
        sv[i] = vp[i];
        int r = i >> 5, t = i & 31;
        skT[t * 50 + r] = kp[i];
    }
    float scale = expf(fminf(logit_scale[hd], LOG100F));
    int widx = w & 255;
    int wh = widx >> 4, ww = widx & 15;
    __syncthreads();

    // fused cosine-norm of q and k rows (1 warp per row)
    int wid = tid >> 5, lane = tid & 31;
    for (int r = wid; r < NTK; r += 8) {
        float qv = sq[r * HDIM + lane];
        float ssq = qv * qv;
#pragma unroll
        for (int o = 16; o; o >>= 1) ssq += __shfl_xor_sync(0xffffffffu, ssq, o);
        sq[r * HDIM + lane] = qv / fmaxf(sqrtf(ssq), 1e-6f);

        float kv = skT[lane * 50 + r];
        float ssk = kv * kv;
#pragma unroll
        for (int o = 16; o; o >>= 1) ssk += __shfl_xor_sync(0xffffffffu, ssk, o);
        skT[lane * 50 + r] = kv / fmaxf(sqrtf(ssk), 1e-6f);
    }
    __syncthreads();

    for (int e = tid; e < NTK * NTK; e += 256) {
        int i = e / NTK, j = e % NTK;
        float s = 0.f;
#pragma unroll 8
        for (int t = 0; t < HDIM; ++t) s = fmaf(sq[i * HDIM + t], skT[t * 50 + j], s);
        int hi = wh * WS + i / WS, wi = ww * WS + i % WS;
        int hj = wh * WS + j / WS, wj = ww * WS + j % WS;
        int idi = (hi < 105 ? 0 : (hi < 109 ? 1 : 2)) * 3 + (wi < 105 ? 0 : (wi < 109 ? 1 : 2));
        int idj = (hj < 105 ? 0 : (hj < 109 ? 1 : 2)) * 3 + (wj < 105 ? 0 : (wj < 109 ? 1 : 2));
        s = fmaf(s, scale, g_rpb[hd * (NTK * NTK) + e]);
        if (idi != idj) s -= 100.0f;
        sS[i * 50 + j] = s;
    }
    __syncthreads();

    for (int r = wid; r < NTK; r += 8) {
        float v0 = sS[r * 50 + lane];
        float v1 = (lane + 32 < NTK) ? sS[r * 50 + lane + 32] : -3.4e38f;
        float m = fmaxf(v0, v1);
#pragma unroll
        for (int o = 16; o; o >>= 1) m = fmaxf(m, __shfl_xor_sync(0xffffffffu, m, o));
        float e0 = expf(v0 - m);
        float e1 = (lane + 32 < NTK) ? expf(v1 - m) : 0.f;
        float s = e0 + e1;
#pragma unroll
        for (int o = 16; o; o >>= 1) s += __shfl_xor_sync(0xffffffffu, s, o);
        float inv = 1.0f / s;
        sS[r * 50 + lane] = e0 * inv;
        if (lane + 32 < NTK) sS[r * 50 + lane + 32] = e1 * inv;
    }
    __syncthreads();

    for (int e = tid; e < NTK * HDIM; e += 256) {
        int i = e >> 5, d = e & 31;
        float acc = 0.f;
#pragma unroll
        for (int j = 0; j < NTK; ++j) acc = fmaf(sS[i * 50 + j], sv[j * HDIM + d], acc);
        out[((size_t)w * NTK + i) * CC + hd * HDIM + d] = acc;
    }
}

// ---------------------------------------------------------------------------
// out = res + LayerNorm(v) * g + b   (1 warp / row of 192)
// ---------------------------------------------------------------------------
__global__ void ln_res_kernel(const float* __restrict__ res, const float* __restrict__ v,
                              const float* __restrict__ g, const float* __restrict__ bb,
                              float* __restrict__ out) {
    int row = blockIdx.x * 8 + (threadIdx.x >> 5);
    int lane = threadIdx.x & 31;
    const float* vp = v + (size_t)row * CC;
    float x[6];
    float s = 0.f;
#pragma unroll
    for (int t = 0; t < 6; ++t) { x[t] = vp[lane + 32 * t]; s += x[t]; }
#pragma unroll
    for (int o = 16; o; o >>= 1) s += __shfl_xor_sync(0xffffffffu, s, o);
    float mean = s * (1.0f / CC);
    float q = 0.f;
#pragma unroll
    for (int t = 0; t < 6; ++t) { float d = x[t] - mean; q += d * d; }
#pragma unroll
    for (int o = 16; o; o >>= 1) q += __shfl_xor_sync(0xffffffffu, q, o);
    float rstd = rsqrtf(q * (1.0f / CC) + 1e-5f);
#pragma unroll
    for (int t = 0; t < 6; ++t) {
        int c = lane + 32 * t;
        out[(size_t)row * CC + c] = res[(size_t)row * CC + c] + (x[t] - mean) * rstd * g[c] + bb[c];
    }
}

// ---------------------------------------------------------------------------
// Launch
// ---------------------------------------------------------------------------
extern "C" void kernel_launch(void* const* d_in, const int* in_sizes, int n_in,
                              void* d_out, int out_size) {
    const float* x      = (const float*)d_in[0];
    const float* q_w    = (const float*)d_in[1];
    const float* q_b    = (const float*)d_in[2];
    const float* k_w    = (const float*)d_in[3];
    const float* v_w    = (const float*)d_in[4];
    const float* v_b    = (const float*)d_in[5];
    const float* proj_w = (const float*)d_in[6];
    const float* proj_b = (const float*)d_in[7];
    const float* lscale = (const float*)d_in[8];
    const float* cpb_w0 = (const float*)d_in[9];
    const float* cpb_b0 = (const float*)d_in[10];
    const float* cpb_w1 = (const float*)d_in[11];
    const float* ln1_g  = (const float*)d_in[12];
    const float* ln1_b  = (const float*)d_in[13];
    const float* ln2_g  = (const float*)d_in[14];
    const float* ln2_b  = (const float*)d_in[15];
    const float* fc1_w  = (const float*)d_in[16];
    const float* fc1_b  = (const float*)d_in[17];
    const float* fc2_w  = (const float*)d_in[18];
    const float* fc2_b  = (const float*)d_in[19];
    float* out = (float*)d_out;

    void* p;
    cudaGetSymbolAddress(&p, g_scratch);
    float* sc    = (float*)p;
    float* hwin  = sc + OFF_HWIN;
    float* qkv   = sc + OFF_QKV;
    float* attno = sc + OFF_ATTNO;
    float* proj  = sc + OFF_PROJ;
    float* h1    = sc + OFF_H1;
    float* mlp1  = sc + OFF_MLP1;
    float* mlp2  = sc + OFF_MLP2;
    cudaGetSymbolAddress(&p, g_wqkv);
    float* wqkv = (float*)p;
    cudaGetSymbolAddress(&p, g_bqkv);
    float* bqkv = (float*)p;

    // rpb table + packed QKV weights
    cpb_kernel<<<(169 * NHD + 255) / 256, 256>>>(cpb_w0, cpb_b0, cpb_w1);
    rpb_kernel<<<(NHD * NTK * NTK + 255) / 256, 256>>>();
    packw_kernel<<<(CC * 3 * CC + 255) / 256, 256>>>(q_w, q_b, k_w, v_w, v_b);

    // shift + window gather
    gather_kernel<<<(MROWS * 48) / 256, 256>>>((const float4*)x, (float4*)hwin);

    // Fused QKV projection (bf16 3-term): scatter to [mat][win][head][n][d]
    dim3 gqkv(3 * CC / TBN, MROWS / TBM);   // 9 x 784
    gemm_tc<EPI_QKV, 0><<<gqkv, 128>>>(hwin, wqkv, bqkv, qkv, 3 * CC, CC);

    // attention (fused q/k norm), fp32 merged-head output (aliases hwin)
    attn_kernel<<<NWIN * NHD, 256>>>(qkv, lscale, attno);

    // output projection (bf16 3-term) + reverse-shift scatter
    dim3 gq(CC / TBN, MROWS / TBM);         // 3 x 784
    gemm_tc<EPI_PROJ, 0><<<gq, 128>>>(attno, proj_w, proj_b, proj, CC, CC);

    // h1 = x + LN(attn_out)
    ln_res_kernel<<<MROWS / 8, 256>>>(x, proj, ln1_g, ln1_b, h1);

    // MLP (fp16 1-term — error diluted by LN2 + residual)
    dim3 g1(HID / TBN, MROWS / TBM);        // 12 x 784
    gemm_tc<EPI_GELU, 1><<<g1, 128>>>(h1, fc1_w, fc1_b, mlp1, HID, CC);
    gemm_tc<EPI_PLAIN, 1><<<gq, 128>>>(mlp1, fc2_w, fc2_b, mlp2, CC, HID);

    // out = h1 + LN(mlp)
    ln_res_kernel<<<MROWS / 8, 256>>>(h1, mlp2, ln2_g, ln2_b, out);
}

// round 14
// speedup vs baseline: 1.0875x; 1.0875x over previous
#include <cuda_runtime.h>
#include <cuda_bf16.h>
#include <cuda_fp16.h>
#include <math.h>
#include <stdint.h>

// ---------------------------------------------------------------------------
// Problem constants
// ---------------------------------------------------------------------------
#define BATCH   8
#define HH      112
#define CC      192
#define WS      7
#define SHIFT   3
#define NHD     6
#define HDIM    32
#define NTK     49
#define NWIN    2048
#define MROWS   100352
#define LTOK    12544
#define HID     768
#define TOKF    19267584ull        // MROWS*CC floats
#define LOG100F 4.6051701859880914f

// ---------------------------------------------------------------------------
// Scratch: ONE static device slab.
//  [0,T)   hwin (alias attno)   [T,4T) qkv q|k|v (q aliased by proj)
//  [4T,5T) h1   [5T,9T) mlp1    [9T,10T) mlp2
// ---------------------------------------------------------------------------
__device__ float g_scratch[10ull * TOKF];
__device__ float g_cpb[169 * NHD];
__device__ float g_rpb[NHD * NTK * NTK];
// Pre-converted weights, k-pair-packed u32, layout [K/2][N]:
__device__ uint32_t g_wqkvH[96 * 576], g_wqkvL[96 * 576];   // bf16 hi/lo
__device__ uint32_t g_wprH[96 * 192],  g_wprL[96 * 192];    // bf16 hi/lo
__device__ uint32_t g_wf1h[96 * 768];                        // fp16
__device__ uint32_t g_wf2h[384 * 192];                       // fp16
__device__ float g_bqkv[3 * CC];

#define OFF_HWIN  (0ull * TOKF)
#define OFF_QKV   (1ull * TOKF)
#define OFF_ATTNO (0ull * TOKF)
#define OFF_PROJ  (1ull * TOKF)
#define OFF_H1    (4ull * TOKF)
#define OFF_MLP1  (5ull * TOKF)
#define OFF_MLP2  (9ull * TOKF)

// ---------------------------------------------------------------------------
// helpers
// ---------------------------------------------------------------------------
__device__ __forceinline__ float gelu_tanh(float x) {
    float x3 = x * x * x;
    return 0.5f * x * (1.0f + tanhf(0.7978845608028654f * (x + 0.044715f * x3)));
}
__device__ __forceinline__ void splitpair(float v0, float v1, uint32_t& hi, uint32_t& lo) {
    __nv_bfloat16 h0 = __float2bfloat16_rn(v0);
    __nv_bfloat16 h1 = __float2bfloat16_rn(v1);
    __nv_bfloat16 l0 = __float2bfloat16_rn(v0 - __bfloat162float(h0));
    __nv_bfloat16 l1 = __float2bfloat16_rn(v1 - __bfloat162float(h1));
    hi = (uint32_t)__bfloat16_as_ushort(h0) | ((uint32_t)__bfloat16_as_ushort(h1) << 16);
    lo = (uint32_t)__bfloat16_as_ushort(l0) | ((uint32_t)__bfloat16_as_ushort(l1) << 16);
}
__device__ __forceinline__ uint32_t h2pack(float v0, float v1) {
    __half2 h = __floats2half2_rn(v0, v1);
    return *(uint32_t*)&h;
}

// ---------------------------------------------------------------------------
// CPB MLP + rpb expansion
// ---------------------------------------------------------------------------
__device__ __forceinline__ float rel_coord(int a) {
    float ch = (float)(a - (WS - 1));
    float t  = ch / (float)(WS - 1) * 8.0f;
    float v  = log2f(fabsf(t) + 1.0f) / log2f(8.0f);
    return (t > 0.f) ? v : ((t < 0.f) ? -v : 0.f);
}
__global__ void cpb_kernel(const float* __restrict__ w0, const float* __restrict__ b0,
                           const float* __restrict__ w1) {
    int idx = blockIdx.x * blockDim.x + threadIdx.x;
    if (idx >= 169 * NHD) return;
    int t = idx / NHD, h = idx % NHD;
    float c0 = rel_coord(t / 13);
    float c1 = rel_coord(t % 13);
    float s = 0.f;
    for (int j = 0; j < 512; ++j) {
        float hid = fmaf(c0, w0[j], fmaf(c1, w0[512 + j], b0[j]));
        hid = fmaxf(hid, 0.f);
        s = fmaf(hid, w1[j * NHD + h], s);
    }
    g_cpb[idx] = 16.0f / (1.0f + expf(-s));
}
__global__ void rpb_kernel() {
    int idx = blockIdx.x * blockDim.x + threadIdx.x;
    if (idx >= NHD * NTK * NTK) return;
    int h = idx / (NTK * NTK), e = idx % (NTK * NTK);
    int i = e / NTK, j = e % NTK;
    int r0 = i / WS - j / WS + (WS - 1);
    int r1 = i % WS - j % WS + (WS - 1);
    g_rpb[idx] = g_cpb[(r0 * 13 + r1) * NHD + h];
}

// ---------------------------------------------------------------------------
// Weight pre-conversion kernels (k-pair-packed u32, [K/2][N])
// ---------------------------------------------------------------------------
__global__ void packqkv_kernel(const float* __restrict__ q_w, const float* __restrict__ q_b,
                               const float* __restrict__ k_w, const float* __restrict__ v_w,
                               const float* __restrict__ v_b) {
    int idx = blockIdx.x * 256 + threadIdx.x;
    if (idx < 96 * 576) {
        int kp = idx / 576, n = idx % 576;
        int mat = n / CC, c = n - mat * CC;
        const float* W = (mat == 0) ? q_w : (mat == 1) ? k_w : v_w;
        uint32_t h, l;
        splitpair(W[(2 * kp) * CC + c], W[(2 * kp + 1) * CC + c], h, l);
        g_wqkvH[idx] = h; g_wqkvL[idx] = l;
    }
    if (idx < 3 * CC)
        g_bqkv[idx] = (idx < CC) ? q_b[idx] : (idx < 2 * CC) ? 0.f : v_b[idx - 2 * CC];
}
__global__ void splitw_kernel(const float* __restrict__ src, uint32_t* __restrict__ dstH,
                              uint32_t* __restrict__ dstL, int K2, int N) {
    int idx = blockIdx.x * 256 + threadIdx.x;
    if (idx >= K2 * N) return;
    int kp = idx / N, n = idx % N;
    uint32_t h, l;
    splitpair(src[(2 * kp) * N + n], src[(2 * kp + 1) * N + n], h, l);
    dstH[idx] = h; dstL[idx] = l;
}
__global__ void halfw_kernel(const float* __restrict__ src, uint32_t* __restrict__ dstH,
                             int K2, int N) {
    int idx = blockIdx.x * 256 + threadIdx.x;
    if (idx >= K2 * N) return;
    int kp = idx / N, n = idx % N;
    dstH[idx] = h2pack(src[(2 * kp) * N + n], src[(2 * kp + 1) * N + n]);
}

// ---------------------------------------------------------------------------
// Shift + window partition gather (float4 wide)
// ---------------------------------------------------------------------------
__global__ void gather_kernel(const float4* __restrict__ x, float4* __restrict__ hwin) {
    int idx = blockIdx.x * 256 + threadIdx.x;                 // over MROWS*48
    if (idx >= MROWS * 48) return;
    int m = idx / 48, c4 = idx % 48;
    int w = m / NTK, n = m % NTK;
    int b = w >> 8, widx = w & 255;
    int wh = widx >> 4, ww = widx & 15;
    int gh = wh * WS + n / WS + SHIFT; if (gh >= HH) gh -= HH;
    int gw = ww * WS + n % WS + SHIFT; if (gw >= HH) gw -= HH;
    hwin[idx] = x[((size_t)(b * LTOK + gh * HH + gw)) * 48 + c4];
}

// ---------------------------------------------------------------------------
// Tensor-core GEMM, fp32 activations in / fp32 out, PRE-CONVERTED weights.
// A: fp32 [M][K] (converted in-loop).  B: u32 k-pair-packed [K/2][N].
// MODE 0: bf16 3-term split (GBKT=16).  MODE 1: fp16 1-term (GBKT=32).
// 128x64 CTA tile, 256 thr (8 warps 4x2), warp tile 32x32, m16n8k16 fp32-acc,
// double-buffered smem, 1 sync per k-tile.
// ---------------------------------------------------------------------------
#define TBM 128
#define TBN 64
#define ASTR 136
#define BSTR 72

enum { EPI_PLAIN = 0, EPI_GELU = 1, EPI_PROJ = 2, EPI_QKV = 3 };

__device__ __forceinline__ void mma_bf16(float c[4], const uint32_t a[4], const uint32_t b[2]) {
    asm volatile(
        "mma.sync.aligned.m16n8k16.row.col.f32.bf16.bf16.f32 "
        "{%0,%1,%2,%3}, {%4,%5,%6,%7}, {%8,%9}, {%0,%1,%2,%3};\n"
        : "+f"(c[0]), "+f"(c[1]), "+f"(c[2]), "+f"(c[3])
        : "r"(a[0]), "r"(a[1]), "r"(a[2]), "r"(a[3]), "r"(b[0]), "r"(b[1]));
}
__device__ __forceinline__ void mma_fp16(float c[4], const uint32_t a[4], const uint32_t b[2]) {
    asm volatile(
        "mma.sync.aligned.m16n8k16.row.col.f32.f16.f16.f32 "
        "{%0,%1,%2,%3}, {%4,%5,%6,%7}, {%8,%9}, {%0,%1,%2,%3};\n"
        : "+f"(c[0]), "+f"(c[1]), "+f"(c[2]), "+f"(c[3])
        : "r"(a[0]), "r"(a[1]), "r"(a[2]), "r"(a[3]), "r"(b[0]), "r"(b[1]));
}

template <int EPI, int MODE, int GBKT>
__global__ __launch_bounds__(256) void gemm_tc(
    const float* __restrict__ A,
    const uint32_t* __restrict__ BH, const uint32_t* __restrict__ BL,
    const float* __restrict__ bias, float* __restrict__ Cout,
    int Nn, int K)
{
    constexpr int KP = GBKT / 2;       // k-pair rows per tile (8 or 16)
    constexpr int APAIRS = KP / 2;     // A k-pairs per thread (4 or 8)
    constexpr int BJ = KP / 4;         // B k-pair rows per thread (2 or 4)

    __shared__ uint32_t AsH[2][KP][ASTR];
    __shared__ uint32_t BsH[2][KP][BSTR];
    __shared__ uint32_t AsL[MODE == 0 ? 2 : 1][MODE == 0 ? KP : 1][MODE == 0 ? ASTR : 1];
    __shared__ uint32_t BsL[MODE == 0 ? 2 : 1][MODE == 0 ? KP : 1][MODE == 0 ? BSTR : 1];

    int tid  = threadIdx.x;
    int lane = tid & 31;
    int wrp  = tid >> 5;
    int warpM = wrp >> 1, warpN = wrp & 1;
    int gr = lane >> 2, tc = lane & 3;
    int bm = blockIdx.y, bn = blockIdx.x;

    // A loader: row = tid>>1, k-segment = (GBKT/2)*(tid&1) floats
    int am = tid >> 1, ab = tid & 1;
    const float* Ap = A + ((size_t)bm * TBM + am) * K + (GBKT / 2) * ab;
    // B loader: col = tid&63, ksel = tid>>6 handles kp rows {ksel + 4j}
    int bcol = tid & 63, ksel = tid >> 6;
    const uint32_t* BpH = BH + bcol + (size_t)bn * TBN;
    const uint32_t* BpL = (MODE == 0) ? (BL + bcol + (size_t)bn * TBN) : nullptr;

    float acc[2][4][4];
#pragma unroll
    for (int mi = 0; mi < 2; ++mi)
#pragma unroll
        for (int ni = 0; ni < 4; ++ni)
#pragma unroll
            for (int e = 0; e < 4; ++e) acc[mi][ni][e] = 0.f;

    float raf[GBKT / 2];
    uint32_t hb[BJ], lb[MODE == 0 ? BJ : 1];

    auto LOAD = [&](int it) {
        int k0 = it * GBKT;
        int kp0 = it * KP;
#pragma unroll
        for (int f = 0; f < GBKT / 8; ++f)
            *(float4*)(raf + 4 * f) = *(const float4*)(Ap + k0 + 4 * f);
#pragma unroll
        for (int j = 0; j < BJ; ++j) {
            int kpj = kp0 + ksel + 4 * j;
            hb[j] = BpH[(size_t)kpj * Nn];
            if constexpr (MODE == 0) lb[j] = BpL[(size_t)kpj * Nn];
        }
    };
    auto STORE = [&](int s) {
#pragma unroll
        for (int i = 0; i < APAIRS; ++i) {
            int kp = APAIRS * ab + i;
            if constexpr (MODE == 0) {
                uint32_t h, l;
                splitpair(raf[2 * i], raf[2 * i + 1], h, l);
                AsH[s][kp][am] = h; AsL[s][kp][am] = l;
            } else {
                AsH[s][kp][am] = h2pack(raf[2 * i], raf[2 * i + 1]);
            }
        }
#pragma unroll
        for (int j = 0; j < BJ; ++j) {
            int kp = ksel + 4 * j;
            BsH[s][kp][bcol] = hb[j];
            if constexpr (MODE == 0) BsL[s][kp][bcol] = lb[j];
        }
    };
    auto COMP = [&](int s) {
#pragma unroll
        for (int step = 0; step < GBKT / 16; ++step) {
            int kb = 8 * step;
            uint32_t aH[2][4], bHf[4][2];
#pragma unroll
            for (int mi = 0; mi < 2; ++mi) {
                int r0 = warpM * 32 + mi * 16 + gr;
                aH[mi][0] = AsH[s][kb + tc][r0];     aH[mi][1] = AsH[s][kb + tc][r0 + 8];
                aH[mi][2] = AsH[s][kb + tc + 4][r0]; aH[mi][3] = AsH[s][kb + tc + 4][r0 + 8];
            }
#pragma unroll
            for (int ni = 0; ni < 4; ++ni) {
                int c0 = warpN * 32 + ni * 8 + gr;
                bHf[ni][0] = BsH[s][kb + tc][c0]; bHf[ni][1] = BsH[s][kb + tc + 4][c0];
            }
            if constexpr (MODE == 0) {
                uint32_t aL[2][4], bLf[4][2];
#pragma unroll
                for (int mi = 0; mi < 2; ++mi) {
                    int r0 = warpM * 32 + mi * 16 + gr;
                    aL[mi][0] = AsL[s][kb + tc][r0];     aL[mi][1] = AsL[s][kb + tc][r0 + 8];
                    aL[mi][2] = AsL[s][kb + tc + 4][r0]; aL[mi][3] = AsL[s][kb + tc + 4][r0 + 8];
                }
#pragma unroll
                for (int ni = 0; ni < 4; ++ni) {
                    int c0 = warpN * 32 + ni * 8 + gr;
                    bLf[ni][0] = BsL[s][kb + tc][c0]; bLf[ni][1] = BsL[s][kb + tc + 4][c0];
                }
#pragma unroll
                for (int mi = 0; mi < 2; ++mi)
#pragma unroll
                    for (int ni = 0; ni < 4; ++ni) {
                        mma_bf16(acc[mi][ni], aH[mi], bLf[ni]);
                        mma_bf16(acc[mi][ni], aL[mi], bHf[ni]);
                        mma_bf16(acc[mi][ni], aH[mi], bHf[ni]);
                    }
            } else {
#pragma unroll
                for (int mi = 0; mi < 2; ++mi)
#pragma unroll
                    for (int ni = 0; ni < 4; ++ni)
                        mma_fp16(acc[mi][ni], aH[mi], bHf[ni]);
            }
        }
    };

    int iters = K / GBKT;
    LOAD(0);
    STORE(0);
    __syncthreads();
    for (int it = 0; it < iters; ++it) {
        int cur = it & 1;
        if (it + 1 < iters) LOAD(it + 1);
        COMP(cur);
        if (it + 1 < iters) STORE(cur ^ 1);
        __syncthreads();
    }

    // epilogue
#pragma unroll
    for (int mi = 0; mi < 2; ++mi) {
        int rbase = bm * TBM + warpM * 32 + mi * 16 + gr;
#pragma unroll
        for (int ni = 0; ni < 4; ++ni) {
            int cbase = bn * TBN + warpN * 32 + ni * 8 + 2 * tc;
#pragma unroll
            for (int e = 0; e < 4; ++e) {
                int row = rbase + (e >> 1) * 8;
                int col = cbase + (e & 1);
                float v = acc[mi][ni][e] + bias[col];
                if constexpr (EPI == EPI_PLAIN) {
                    Cout[(size_t)row * Nn + col] = v;
                } else if constexpr (EPI == EPI_GELU) {
                    Cout[(size_t)row * Nn + col] = gelu_tanh(v);
                } else if constexpr (EPI == EPI_PROJ) {
                    int w = row / NTK, n = row % NTK;
                    int b = w >> 8, widx = w & 255;
                    int wh = widx >> 4, ww = widx & 15;
                    int gh = wh * WS + n / WS + SHIFT; if (gh >= HH) gh -= HH;
                    int gw = ww * WS + n % WS + SHIFT; if (gw >= HH) gw -= HH;
                    Cout[((size_t)(b * LTOK + gh * HH + gw)) * CC + col] = v;
                } else {  // EPI_QKV: col in [0,576); mat = col/192
                    int mat = col / CC, c = col - mat * CC;
                    int head = c >> 5, d = c & 31;
                    int w = row / NTK, n = row % NTK;
                    size_t off = (size_t)mat * TOKF +
                                 (((size_t)w * NHD + head) * NTK + n) * HDIM + d;
                    Cout[off] = v;
                }
            }
        }
    }
}

// ---------------------------------------------------------------------------
// Attention: fused q/k cosine-normalize + scores + softmax + PV (all fp32).
// ---------------------------------------------------------------------------
__global__ __launch_bounds__(256) void attn_kernel(
    const float* __restrict__ qkv, const float* __restrict__ logit_scale,
    float* __restrict__ out)
{
    __shared__ float sq[NTK * HDIM];
    __shared__ float skT[HDIM * 50];
    __shared__ float sv[NTK * HDIM];
    __shared__ float sS[NTK * 50];

    int bid = blockIdx.x;
    int w = bid / NHD, hd = bid % NHD;
    size_t base = ((size_t)w * NHD + hd) * (NTK * HDIM);
    const float* qp = qkv + base;
    const float* kp = qkv + TOKF + base;
    const float* vp = qkv + 2ull * TOKF + base;

    int tid = threadIdx.x;
    for (int i = tid; i < NTK * HDIM; i += 256) {
        sq[i] = qp[i];
        sv[i] = vp[i];
        int r = i >> 5, t = i & 31;
        skT[t * 50 + r] = kp[i];
    }
    float scale = expf(fminf(logit_scale[hd], LOG100F));
    int widx = w & 255;
    int wh = widx >> 4, ww = widx & 15;
    __syncthreads();

    // fused cosine-norm of q and k rows (1 warp per row)
    int wid = tid >> 5, lane = tid & 31;
    for (int r = wid; r < NTK; r += 8) {
        float qv = sq[r * HDIM + lane];
        float ssq = qv * qv;
#pragma unroll
        for (int o = 16; o; o >>= 1) ssq += __shfl_xor_sync(0xffffffffu, ssq, o);
        sq[r * HDIM + lane] = qv / fmaxf(sqrtf(ssq), 1e-6f);

        float kv = skT[lane * 50 + r];
        float ssk = kv * kv;
#pragma unroll
        for (int o = 16; o; o >>= 1) ssk += __shfl_xor_sync(0xffffffffu, ssk, o);
        skT[lane * 50 + r] = kv / fmaxf(sqrtf(ssk), 1e-6f);
    }
    __syncthreads();

    for (int e = tid; e < NTK * NTK; e += 256) {
        int i = e / NTK, j = e % NTK;
        float s = 0.f;
#pragma unroll 8
        for (int t = 0; t < HDIM; ++t) s = fmaf(sq[i * HDIM + t], skT[t * 50 + j], s);
        int hi = wh * WS + i / WS, wi = ww * WS + i % WS;
        int hj = wh * WS + j / WS, wj = ww * WS + j % WS;
        int idi = (hi < 105 ? 0 : (hi < 109 ? 1 : 2)) * 3 + (wi < 105 ? 0 : (wi < 109 ? 1 : 2));
        int idj = (hj < 105 ? 0 : (hj < 109 ? 1 : 2)) * 3 + (wj < 105 ? 0 : (wj < 109 ? 1 : 2));
        s = fmaf(s, scale, g_rpb[hd * (NTK * NTK) + e]);
        if (idi != idj) s -= 100.0f;
        sS[i * 50 + j] = s;
    }
    __syncthreads();

    for (int r = wid; r < NTK; r += 8) {
        float v0 = sS[r * 50 + lane];
        float v1 = (lane + 32 < NTK) ? sS[r * 50 + lane + 32] : -3.4e38f;
        float m = fmaxf(v0, v1);
#pragma unroll
        for (int o = 16; o; o >>= 1) m = fmaxf(m, __shfl_xor_sync(0xffffffffu, m, o));
        float e0 = expf(v0 - m);
        float e1 = (lane + 32 < NTK) ? expf(v1 - m) : 0.f;
        float s = e0 + e1;
#pragma unroll
        for (int o = 16; o; o >>= 1) s += __shfl_xor_sync(0xffffffffu, s, o);
        float inv = 1.0f / s;
        sS[r * 50 + lane] = e0 * inv;
        if (lane + 32 < NTK) sS[r * 50 + lane + 32] = e1 * inv;
    }
    __syncthreads();

    for (int e = tid; e < NTK * HDIM; e += 256) {
        int i = e >> 5, d = e & 31;
        float acc = 0.f;
#pragma unroll
        for (int j = 0; j < NTK; ++j) acc = fmaf(sS[i * 50 + j], sv[j * HDIM + d], acc);
        out[((size_t)w * NTK + i) * CC + hd * HDIM + d] = acc;
    }
}

// ---------------------------------------------------------------------------
// out = res + LayerNorm(v) * g + b   (1 warp / row of 192)
// ---------------------------------------------------------------------------
__global__ void ln_res_kernel(const float* __restrict__ res, const float* __restrict__ v,
                              const float* __restrict__ g, const float* __restrict__ bb,
                              float* __restrict__ out) {
    int row = blockIdx.x * 8 + (threadIdx.x >> 5);
    int lane = threadIdx.x & 31;
    const float* vp = v + (size_t)row * CC;
    float x[6];
    float s = 0.f;
#pragma unroll
    for (int t = 0; t < 6; ++t) { x[t] = vp[lane + 32 * t]; s += x[t]; }
#pragma unroll
    for (int o = 16; o; o >>= 1) s += __shfl_xor_sync(0xffffffffu, s, o);
    float mean = s * (1.0f / CC);
    float q = 0.f;
#pragma unroll
    for (int t = 0; t < 6; ++t) { float d = x[t] - mean; q += d * d; }
#pragma unroll
    for (int o = 16; o; o >>= 1) q += __shfl_xor_sync(0xffffffffu, q, o);
    float rstd = rsqrtf(q * (1.0f / CC) + 1e-5f);
#pragma unroll
    for (int t = 0; t < 6; ++t) {
        int c = lane + 32 * t;
        out[(size_t)row * CC + c] = res[(size_t)row * CC + c] + (x[t] - mean) * rstd * g[c] + bb[c];
    }
}

// ---------------------------------------------------------------------------
// Launch
// ---------------------------------------------------------------------------
extern "C" void kernel_launch(void* const* d_in, const int* in_sizes, int n_in,
                              void* d_out, int out_size) {
    const float* x      = (const float*)d_in[0];
    const float* q_w    = (const float*)d_in[1];
    const float* q_b    = (const float*)d_in[2];
    const float* k_w    = (const float*)d_in[3];
    const float* v_w    = (const float*)d_in[4];
    const float* v_b    = (const float*)d_in[5];
    const float* proj_w = (const float*)d_in[6];
    const float* proj_b = (const float*)d_in[7];
    const float* lscale = (const float*)d_in[8];
    const float* cpb_w0 = (const float*)d_in[9];
    const float* cpb_b0 = (const float*)d_in[10];
    const float* cpb_w1 = (const float*)d_in[11];
    const float* ln1_g  = (const float*)d_in[12];
    const float* ln1_b  = (const float*)d_in[13];
    const float* ln2_g  = (const float*)d_in[14];
    const float* ln2_b  = (const float*)d_in[15];
    const float* fc1_w  = (const float*)d_in[16];
    const float* fc1_b  = (const float*)d_in[17];
    const float* fc2_w  = (const float*)d_in[18];
    const float* fc2_b  = (const float*)d_in[19];
    float* out = (float*)d_out;

    void* p;
    cudaGetSymbolAddress(&p, g_scratch);
    float* sc    = (float*)p;
    float* hwin  = sc + OFF_HWIN;
    float* qkv   = sc + OFF_QKV;
    float* attno = sc + OFF_ATTNO;
    float* proj  = sc + OFF_PROJ;
    float* h1    = sc + OFF_H1;
    float* mlp1  = sc + OFF_MLP1;
    float* mlp2  = sc + OFF_MLP2;

    uint32_t *wqH, *wqL, *wpH, *wpL, *w1h, *w2h;
    float* bqkv;
    cudaGetSymbolAddress(&p, g_wqkvH); wqH = (uint32_t*)p;
    cudaGetSymbolAddress(&p, g_wqkvL); wqL = (uint32_t*)p;
    cudaGetSymbolAddress(&p, g_wprH);  wpH = (uint32_t*)p;
    cudaGetSymbolAddress(&p, g_wprL);  wpL = (uint32_t*)p;
    cudaGetSymbolAddress(&p, g_wf1h);  w1h = (uint32_t*)p;
    cudaGetSymbolAddress(&p, g_wf2h);  w2h = (uint32_t*)p;
    cudaGetSymbolAddress(&p, g_bqkv);  bqkv = (float*)p;

    // rpb table + pre-converted weights
    cpb_kernel<<<(169 * NHD + 255) / 256, 256>>>(cpb_w0, cpb_b0, cpb_w1);
    rpb_kernel<<<(NHD * NTK * NTK + 255) / 256, 256>>>();
    packqkv_kernel<<<(96 * 576 + 255) / 256, 256>>>(q_w, q_b, k_w, v_w, v_b);
    splitw_kernel<<<(96 * 192 + 255) / 256, 256>>>(proj_w, wpH, wpL, 96, 192);
    halfw_kernel<<<(96 * 768 + 255) / 256, 256>>>(fc1_w, w1h, 96, 768);
    halfw_kernel<<<(384 * 192 + 255) / 256, 256>>>(fc2_w, w2h, 384, 192);

    // shift + window gather
    gather_kernel<<<(MROWS * 48) / 256, 256>>>((const float4*)x, (float4*)hwin);

    // Fused QKV projection (bf16 3-term, GBK16): scatter to [mat][win][head][n][d]
    gemm_tc<EPI_QKV, 0, 16><<<dim3(9, MROWS / TBM), 256>>>(hwin, wqH, wqL, bqkv,
                                                           qkv, 3 * CC, CC);

    // attention (fused q/k norm), fp32 merged-head output (aliases hwin)
    attn_kernel<<<NWIN * NHD, 256>>>(qkv, lscale, attno);

    // output projection (bf16 3-term, GBK16) + reverse-shift scatter
    gemm_tc<EPI_PROJ, 0, 16><<<dim3(3, MROWS / TBM), 256>>>(attno, wpH, wpL, proj_b,
                                                            proj, CC, CC);

    // h1 = x + LN(attn_out)
    ln_res_kernel<<<MROWS / 8, 256>>>(x, proj, ln1_g, ln1_b, h1);

    // MLP (fp16 1-term, GBK32 — halved syncs)
    gemm_tc<EPI_GELU, 1, 32><<<dim3(12, MROWS / TBM), 256>>>(h1, w1h, nullptr, fc1_b,
                                                             mlp1, HID, CC);
    gemm_tc<EPI_PLAIN, 1, 32><<<dim3(3, MROWS / TBM), 256>>>(mlp1, w2h, nullptr, fc2_b,
                                                             mlp2, CC, HID);

    // out = h1 + LN(mlp)
    ln_res_kernel<<<MROWS / 8, 256>>>(h1, mlp2, ln2_g, ln2_b, out);
}